// round 2
// baseline (speedup 1.0000x reference)
#include <cuda_runtime.h>
#include <cuda_bf16.h>

// Problem constants (shapes are fixed by the dataset)
#define DFEAT 256
#define DFEAT4 (DFEAT / 4)

// Scratch (no cudaMalloc allowed -> device globals)
__device__ float g_agg[10000 * DFEAT];
__device__ float g_h1[10000 * DFEAT];

// ---------------------------------------------------------------------------
// Kernel 1: agg = x  (so after scatter, agg holds x_i + sum_j x_j, eps=0)
// ---------------------------------------------------------------------------
__global__ void init_agg_kernel(const float* __restrict__ x, float* __restrict__ agg, int total4) {
    int i = blockIdx.x * blockDim.x + threadIdx.x;
    if (i < total4) {
        ((float4*)agg)[i] = ((const float4*)x)[i];
    }
}

// ---------------------------------------------------------------------------
// Kernel 2: scatter-add x[src] into agg[dst] using vectorized red.global.v4
// Each edge is handled by 64 threads (one float4 chunk each).
// Edge index dtype (int64 vs int32) is detected at runtime.
// ---------------------------------------------------------------------------
__global__ void scatter_kernel(const float* __restrict__ x,
                               const void* __restrict__ eidx,
                               float* __restrict__ agg,
                               int E) {
    __shared__ int s_is64;
    if (threadIdx.x == 0) {
        const int* e32 = (const int*)eidx;
        int any = 0;
#pragma unroll
        for (int k = 0; k < 8; k++) any |= e32[2 * k + 1];
        // int64 values < 2^31 and nonnegative -> all high words are zero
        s_is64 = (any == 0) ? 1 : 0;
    }
    __syncthreads();
    const int is64 = s_is64;

    int tid = blockIdx.x * blockDim.x + threadIdx.x;
    int e = tid >> 6;       // edge id
    int c = tid & 63;       // float4 chunk within the 256-float row
    if (e >= E) return;

    int src, dst;
    if (is64) {
        const long long* e64 = (const long long*)eidx;
        src = (int)e64[e];
        dst = (int)e64[E + e];
    } else {
        const int* e32 = (const int*)eidx;
        src = e32[e];
        dst = e32[E + e];
    }

    float4 v = ((const float4*)x)[src * DFEAT4 + c];
    float* p = agg + (size_t)dst * DFEAT + c * 4;
    asm volatile("red.global.add.v4.f32 [%0], {%1,%2,%3,%4};"
                 :: "l"(p), "f"(v.x), "f"(v.y), "f"(v.z), "f"(v.w)
                 : "memory");
}

// ---------------------------------------------------------------------------
// Kernel 3: tiled fp32 GEMM with bias (+ optional ReLU)
//   C[M,256] = act(A[M,256] @ W[256,256] + bias)
// 128x128 block tile, BK=16, 256 threads, 8x8 micro-tile per thread.
// ---------------------------------------------------------------------------
template <bool RELU>
__global__ void __launch_bounds__(256) gemm_bias_kernel(
    const float* __restrict__ A, const float* __restrict__ W,
    const float* __restrict__ bias, float* __restrict__ C, int M) {

    __shared__ float As[16][128];   // As[k][m]
    __shared__ float Bs[16][128];   // Bs[k][n]

    const int tid = threadIdx.x;
    const int tx = tid & 15;        // -> n block (8 cols)
    const int ty = tid >> 4;        // -> m block (8 rows)
    const int row0 = blockIdx.x * 128;
    const int col0 = blockIdx.y * 128;

    // A staging: thread loads 8 consecutive k for one row m
    const int am = tid >> 1;            // 0..127
    const int ak = (tid & 1) * 8;       // 0 or 8
    // B staging: thread loads one float4 of a row, two rows
    const int bn = (tid & 31) * 4;      // 0..124
    const int bk = tid >> 5;            // 0..7

    float acc[8][8];
#pragma unroll
    for (int i = 0; i < 8; i++)
#pragma unroll
        for (int j = 0; j < 8; j++) acc[i][j] = 0.0f;

    for (int k0 = 0; k0 < 256; k0 += 16) {
        const int arow = row0 + am;
        float4 a0, a1;
        if (arow < M) {
            const float* ap = A + (size_t)arow * 256 + k0 + ak;
            a0 = *(const float4*)(ap);
            a1 = *(const float4*)(ap + 4);
        } else {
            a0 = make_float4(0.f, 0.f, 0.f, 0.f);
            a1 = a0;
        }
        const float* wp = W + (size_t)(k0 + bk) * 256 + col0 + bn;
        float4 b0 = *(const float4*)(wp);
        float4 b1 = *(const float4*)(wp + 8 * 256);

        __syncthreads();
        As[ak + 0][am] = a0.x; As[ak + 1][am] = a0.y;
        As[ak + 2][am] = a0.z; As[ak + 3][am] = a0.w;
        As[ak + 4][am] = a1.x; As[ak + 5][am] = a1.y;
        As[ak + 6][am] = a1.z; As[ak + 7][am] = a1.w;
        *(float4*)&Bs[bk][bn] = b0;
        *(float4*)&Bs[bk + 8][bn] = b1;
        __syncthreads();

#pragma unroll
        for (int k = 0; k < 16; k++) {
            float4 af0 = *(const float4*)&As[k][ty * 8];
            float4 af1 = *(const float4*)&As[k][ty * 8 + 4];
            float4 bf0 = *(const float4*)&Bs[k][tx * 8];
            float4 bf1 = *(const float4*)&Bs[k][tx * 8 + 4];
            float a[8] = {af0.x, af0.y, af0.z, af0.w, af1.x, af1.y, af1.z, af1.w};
            float b[8] = {bf0.x, bf0.y, bf0.z, bf0.w, bf1.x, bf1.y, bf1.z, bf1.w};
#pragma unroll
            for (int i = 0; i < 8; i++)
#pragma unroll
                for (int j = 0; j < 8; j++)
                    acc[i][j] = fmaf(a[i], b[j], acc[i][j]);
        }
    }

#pragma unroll
    for (int i = 0; i < 8; i++) {
        const int r = row0 + ty * 8 + i;
        if (r < M) {
#pragma unroll
            for (int j = 0; j < 8; j += 4) {
                const int c = col0 + tx * 8 + j;
                float4 v;
                v.x = acc[i][j + 0] + bias[c + 0];
                v.y = acc[i][j + 1] + bias[c + 1];
                v.z = acc[i][j + 2] + bias[c + 2];
                v.w = acc[i][j + 3] + bias[c + 3];
                if (RELU) {
                    v.x = fmaxf(v.x, 0.f); v.y = fmaxf(v.y, 0.f);
                    v.z = fmaxf(v.z, 0.f); v.w = fmaxf(v.w, 0.f);
                }
                *(float4*)&C[(size_t)r * 256 + c] = v;
            }
        }
    }
}

// ---------------------------------------------------------------------------
// Launch
// ---------------------------------------------------------------------------
extern "C" void kernel_launch(void* const* d_in, const int* in_sizes, int n_in,
                              void* d_out, int out_size) {
    const float* x    = (const float*)d_in[0];
    const void*  eidx = d_in[1];
    const float* W1   = (const float*)d_in[2];
    const float* b1   = (const float*)d_in[3];
    const float* W2   = (const float*)d_in[4];
    const float* b2   = (const float*)d_in[5];
    float* out = (float*)d_out;

    const int M = in_sizes[0] / DFEAT;   // number of nodes (10000)
    const int E = in_sizes[1] / 2;       // number of edges (320000)

    float* agg = nullptr;
    float* h1  = nullptr;
    cudaGetSymbolAddress((void**)&agg, g_agg);
    cudaGetSymbolAddress((void**)&h1, g_h1);

    // 1) agg = x
    const int total4 = M * DFEAT4;
    init_agg_kernel<<<(total4 + 255) / 256, 256>>>(x, agg, total4);

    // 2) agg += scatter(x[src] -> dst)
    const long long work = (long long)E * 64;
    const int sblocks = (int)((work + 255) / 256);
    scatter_kernel<<<sblocks, 256>>>(x, eidx, agg, E);

    // 3) h1 = relu(agg @ W1 + b1)
    dim3 ggrid((M + 127) / 128, 2);
    gemm_bias_kernel<true><<<ggrid, 256>>>(agg, W1, b1, h1, M);

    // 4) out = h1 @ W2 + b2
    gemm_bias_kernel<false><<<ggrid, 256>>>(h1, W2, b2, out, M);
}